// round 1
// baseline (speedup 1.0000x reference)
#include <cuda_runtime.h>
#include <cstdint>
#include <cstddef>

#define N_NODES 8192
#define N_GRAPHS 128
#define NPG 64
#define N_EDGES 131072
#define EPG 1024
#define HL 256

// ---------------- scratch (device globals; no allocations) ----------------
__device__ float g_buf1[N_NODES * 640];
__device__ float g_buf2[N_NODES * 640];
__device__ float g_pre [N_NODES * 1024];
__device__ float g_scale[640];
__device__ float g_shift[640];
__device__ int   g_rowptr[N_GRAPHS * 65];
__device__ int   g_csr_src[N_EDGES];
__device__ float g_csr_w [N_EDGES];
__device__ float g_biaslstm[1024];
__device__ float g_pool[N_GRAPHS * HL];

__device__ __forceinline__ float leakyf(float v) { return v >= 0.f ? v : 0.01f * v; }
__device__ __forceinline__ float sigf(float x)   { return 1.f / (1.f + __expf(-x)); }
__device__ __forceinline__ float tanh_fast(float x) { return 2.f / (1.f + __expf(-2.f * x)) - 1.f; }

// ---------------- deterministic per-graph CSR build ----------------
__global__ __launch_bounds__(256) void csr_build(const int* __restrict__ ei,
                                                 const float* __restrict__ ew)
{
    int g = blockIdx.x, tid = threadIdx.x;
    __shared__ unsigned char s_dl[EPG];
    __shared__ unsigned char s_sl[EPG];
    __shared__ float s_ew[EPG];
    __shared__ int s_cnt[64];
    __shared__ int s_off[65];

    const int* src = ei + (size_t)g * EPG;
    const int* dst = ei + N_EDGES + (size_t)g * EPG;
    for (int e = tid; e < EPG; e += 256) {
        s_dl[e] = (unsigned char)(dst[e] & 63);
        s_sl[e] = (unsigned char)(src[e] & 63);
        s_ew[e] = ew[(size_t)g * EPG + e];
    }
    __syncthreads();
    if (tid < 64) {
        int c = 0;
        for (int e = 0; e < EPG; e++) c += (s_dl[e] == tid);
        s_cnt[tid] = c;
    }
    __syncthreads();
    if (tid == 0) {
        int s = 0;
        for (int i = 0; i < 64; i++) { s_off[i] = s; s += s_cnt[i]; }
        s_off[64] = s;
    }
    __syncthreads();
    if (tid < 65) g_rowptr[g * 65 + tid] = s_off[tid];
    if (tid < 64) {
        int p = s_off[tid];
        for (int e = 0; e < EPG; e++) {
            if (s_dl[e] == tid) {
                g_csr_src[g * EPG + p] = s_sl[e];
                g_csr_w [g * EPG + p] = s_ew[e];
                p++;
            }
        }
    }
}

// ---------------- GEMM: C[M,N] = A[M,K] @ B[N,K]^T (+bias[n]) ----------------
#define GBM 128
#define GBN 64
#define GBK 16
__global__ __launch_bounds__(256) void gemm_tn(const float* __restrict__ A,
                                               const float* __restrict__ B,
                                               float* __restrict__ C,
                                               const float* __restrict__ bias,
                                               int M, int N, int K)
{
    __shared__ float As[GBK][GBM];
    __shared__ float Bs[GBK][GBN + 4];
    int tid = threadIdx.x;
    int tx = tid & 15, ty = tid >> 4;
    int m0 = blockIdx.y * GBM, n0 = blockIdx.x * GBN;

    float acc[8][4];
#pragma unroll
    for (int i = 0; i < 8; i++)
#pragma unroll
        for (int j = 0; j < 4; j++) acc[i][j] = 0.f;

    for (int kt = 0; kt < K; kt += GBK) {
        __syncthreads();
#pragma unroll
        for (int l = 0; l < 2; l++) {
            int idx = tid + l * 256;
            int row = idx >> 2, kq = idx & 3;
            float4 v = *(const float4*)&A[(size_t)(m0 + row) * K + kt + kq * 4];
            As[kq * 4 + 0][row] = v.x; As[kq * 4 + 1][row] = v.y;
            As[kq * 4 + 2][row] = v.z; As[kq * 4 + 3][row] = v.w;
        }
        {
            int row = tid >> 2, kq = tid & 3;
            float4 v = *(const float4*)&B[(size_t)(n0 + row) * K + kt + kq * 4];
            Bs[kq * 4 + 0][row] = v.x; Bs[kq * 4 + 1][row] = v.y;
            Bs[kq * 4 + 2][row] = v.z; Bs[kq * 4 + 3][row] = v.w;
        }
        __syncthreads();
#pragma unroll
        for (int k = 0; k < GBK; k++) {
            float4 a0 = *(const float4*)&As[k][ty * 8];
            float4 a1 = *(const float4*)&As[k][ty * 8 + 4];
            float4 b  = *(const float4*)&Bs[k][tx * 4];
            float av[8] = {a0.x, a0.y, a0.z, a0.w, a1.x, a1.y, a1.z, a1.w};
            float bv[4] = {b.x, b.y, b.z, b.w};
#pragma unroll
            for (int i = 0; i < 8; i++)
#pragma unroll
                for (int j = 0; j < 4; j++) acc[i][j] += av[i] * bv[j];
        }
    }

    float bb[4] = {0.f, 0.f, 0.f, 0.f};
    if (bias) {
#pragma unroll
        for (int j = 0; j < 4; j++) bb[j] = bias[n0 + tx * 4 + j];
    }
#pragma unroll
    for (int i = 0; i < 8; i++) {
        int m = m0 + ty * 8 + i;
        float4 o;
        o.x = acc[i][0] + bb[0];
        o.y = acc[i][1] + bb[1];
        o.z = acc[i][2] + bb[2];
        o.w = acc[i][3] + bb[3];
        *(float4*)&C[(size_t)m * N + n0 + tx * 4] = o;
    }
}

// ---------------- GCN aggregation: gather via CSR, *ew, +bias ----------------
__global__ __launch_bounds__(256) void gcn_agg(const float* __restrict__ lin,
                                               const float* __restrict__ bias,
                                               float* __restrict__ out, int F)
{
    int g = blockIdx.y;
    int cb = blockIdx.x * 64;
    __shared__ float s_in[64][64];
    __shared__ float s_w[EPG];
    __shared__ int   s_src[EPG];
    __shared__ int   s_rp[65];
    int tid = threadIdx.x;

    for (int i = tid; i < 1024; i += 256) {
        int row = i >> 4, cq = i & 15;
        *(float4*)&s_in[row][cq * 4] =
            *(const float4*)&lin[(size_t)(g * 64 + row) * F + cb + cq * 4];
    }
    for (int e = tid; e < EPG; e += 256) {
        s_src[e] = g_csr_src[g * EPG + e];
        s_w[e]   = g_csr_w [g * EPG + e];
    }
    if (tid < 65) s_rp[tid] = g_rowptr[g * 65 + tid];
    __syncthreads();

    int f = tid & 63;
    int d0 = tid >> 6;
    float bv = bias[cb + f];
    for (int d = d0; d < 64; d += 4) {
        float acc = 0.f;
        int e0 = s_rp[d], e1 = s_rp[d + 1];
        for (int e = e0; e < e1; e++) acc += s_in[s_src[e]][f] * s_w[e];
        out[(size_t)(g * 64 + d) * F + cb + f] = acc + bv;
    }
}

// ---------------- BN batch stats -> per-column scale/shift ----------------
__global__ __launch_bounds__(256) void bn_stats(const float* __restrict__ a,
                                                const float* __restrict__ gamma,
                                                const float* __restrict__ beta,
                                                float* __restrict__ scale,
                                                float* __restrict__ shift, int F)
{
    int lane = threadIdx.x & 31;
    int col = blockIdx.x * 32 + lane;
    int rg = threadIdx.x >> 5;
    float s = 0.f, s2 = 0.f;
    for (int row = rg; row < N_NODES; row += 8) {
        float v = a[(size_t)row * F + col];
        s += v; s2 += v * v;
    }
    __shared__ float sh[8][32], sh2[8][32];
    sh[rg][lane] = s; sh2[rg][lane] = s2;
    __syncthreads();
    if (rg == 0) {
#pragma unroll
        for (int i = 1; i < 8; i++) { s += sh[i][lane]; s2 += sh2[i][lane]; }
        float mu  = s * (1.f / N_NODES);
        float var = s2 * (1.f / N_NODES) - mu * mu;
        float inv = rsqrtf(var + 1e-5f);
        float gsc = gamma[col] * inv;
        scale[col] = gsc;
        shift[col] = beta[col] - mu * gsc;
    }
}

__global__ void norm_leaky(float* __restrict__ a, const float* __restrict__ scale,
                           const float* __restrict__ shift, int F, int total)
{
    int i = blockIdx.x * blockDim.x + threadIdx.x;
    if (i < total) {
        int c = i % F;
        float v = a[i] * scale[c] + shift[c];
        a[i] = leakyf(v);
    }
}

__global__ void add_vec(const float* __restrict__ a, const float* __restrict__ b,
                        float* __restrict__ o, int n)
{
    int i = blockIdx.x * blockDim.x + threadIdx.x;
    if (i < n) o[i] = a[i] + b[i];
}

// ---------------- LSTM: 8-CTA cluster, Whh register-resident ----------------
__global__ void __launch_bounds__(512, 1) __cluster_dims__(8, 1, 1)
lstm_kernel(const float* __restrict__ Whh, const float* __restrict__ pre,
            float* __restrict__ pool)
{
    __shared__ float h_s[256];
    __shared__ float c_s[256];
    __shared__ float gates_s[2][1024];
    __shared__ float pa_s[256];

    int tid = threadIdx.x;
    unsigned rank;
    asm("mov.u32 %0, %%cluster_ctarank;" : "=r"(rank));
    int row_local = tid >> 2;            // 0..127
    int quad = tid & 3;                  // column segment selector
    int r = (int)rank * 128 + row_local; // global gate row 0..1023
    int gtype = r >> 8;                  // 0:i 1:f 2:g 3:o

    // register-resident weights: cols quad*2 + 8*m + {0,1}
    float2 w[32];
    {
        const float* wr = Whh + (size_t)r * 256 + quad * 2;
#pragma unroll
        for (int m = 0; m < 32; m++) w[m] = *(const float2*)(wr + 8 * m);
    }

    if (tid < 256) { h_s[tid] = 0.f; c_s[tid] = 0.f; pa_s[tid] = 0.f; }
    float pre_next = 0.f;
    if (quad == 0) pre_next = __ldg(&pre[r]);
    __syncthreads();

    for (int t = 0; t < N_NODES; ++t) {
        float pre_cur = pre_next;
        if (quad == 0 && t + 1 < N_NODES) pre_next = __ldg(&pre[(size_t)(t + 1) * 1024 + r]);

        // phase A: partial dot over this thread's 64 columns
        float acc = 0.f;
        const float* hp = h_s + quad * 2;
#pragma unroll
        for (int m = 0; m < 32; m++) {
            float2 hv = *(const float2*)(hp + 8 * m);
            acc += w[m].x * hv.x;
            acc += w[m].y * hv.y;
        }
        acc += __shfl_xor_sync(0xffffffffu, acc, 1);
        acc += __shfl_xor_sync(0xffffffffu, acc, 2);

        if (quad == 0) {
            float gg = acc + pre_cur;
            float v = (gtype == 2) ? tanh_fast(gg) : sigf(gg);
            unsigned laddr = (unsigned)__cvta_generic_to_shared(&gates_s[t & 1][r]);
#pragma unroll
            for (int c2 = 0; c2 < 8; c2++) {
                unsigned raddr;
                asm volatile("mapa.shared::cluster.u32 %0, %1, %2;"
                             : "=r"(raddr) : "r"(laddr), "r"(c2));
                asm volatile("st.shared::cluster.f32 [%0], %1;"
                             :: "r"(raddr), "f"(v) : "memory");
            }
        }

        asm volatile("barrier.cluster.arrive.aligned;" ::: "memory");
        asm volatile("barrier.cluster.wait.aligned;" ::: "memory");

        // phase B: every CTA redundantly updates full c,h (local smem)
        if (tid < 256) {
            const float* gb = &gates_s[t & 1][0];
            float iv = gb[tid], fv = gb[256 + tid], gv = gb[512 + tid], ov = gb[768 + tid];
            float cc = fv * c_s[tid] + iv * gv;
            float hh = ov * tanh_fast(cc);
            c_s[tid] = cc;
            h_s[tid] = hh;
            int g = t >> 6;
            if ((unsigned)(g & 7) == rank) {
                float p = pa_s[tid] + hh;
                if ((t & 63) == 63) { pool[(size_t)g * 256 + tid] = p; p = 0.f; }
                pa_s[tid] = p;
            }
        }
        __syncthreads();
    }
}

// ---------------- head MLP: per-graph 256->128->64->2, all leaky ----------------
__global__ __launch_bounds__(128) void fc_head(const float* __restrict__ pool,
                                               const float* __restrict__ fW1, const float* __restrict__ fb1,
                                               const float* __restrict__ fW2, const float* __restrict__ fb2,
                                               const float* __restrict__ fW3, const float* __restrict__ fb3,
                                               float* __restrict__ out)
{
    int g = blockIdx.x, t = threadIdx.x;
    __shared__ float p[256], s1[128], s2[64];
    p[t] = pool[(size_t)g * 256 + t];
    p[t + 128] = pool[(size_t)g * 256 + t + 128];
    __syncthreads();
    float a1 = fb1[t];
    for (int k = 0; k < 256; k++) a1 += p[k] * fW1[(size_t)t * 256 + k];
    s1[t] = leakyf(a1);
    __syncthreads();
    if (t < 64) {
        float a2 = fb2[t];
        for (int k = 0; k < 128; k++) a2 += s1[k] * fW2[(size_t)t * 128 + k];
        s2[t] = leakyf(a2);
    }
    __syncthreads();
    if (t < 2) {
        float a3 = fb3[t];
        for (int k = 0; k < 64; k++) a3 += s2[k] * fW3[(size_t)t * 64 + k];
        out[(size_t)g * 2 + t] = leakyf(a3);
    }
}

// ---------------- host side ----------------
static float* symf(const void* sym) { void* p = nullptr; cudaGetSymbolAddress(&p, sym); return (float*)p; }

extern "C" void kernel_launch(void* const* d_in, const int* in_sizes, int n_in,
                              void* d_out, int out_size)
{
    const float* x   = (const float*)d_in[0];
    const int*   ei  = (const int*)  d_in[1];
    const float* ew  = (const float*)d_in[2];
    // d_in[3] = batch (implicit by construction)
    const float* W1  = (const float*)d_in[4];
    const float* b1  = (const float*)d_in[5];
    const float* ga1 = (const float*)d_in[6];
    const float* be1 = (const float*)d_in[7];
    const float* W2  = (const float*)d_in[8];
    const float* b2  = (const float*)d_in[9];
    const float* ga2 = (const float*)d_in[10];
    const float* be2 = (const float*)d_in[11];
    const float* W3  = (const float*)d_in[12];
    const float* b3  = (const float*)d_in[13];
    const float* ga3 = (const float*)d_in[14];
    const float* be3 = (const float*)d_in[15];
    const float* Wih = (const float*)d_in[16];
    const float* Whh = (const float*)d_in[17];
    const float* bih = (const float*)d_in[18];
    const float* bhh = (const float*)d_in[19];
    const float* fW1 = (const float*)d_in[20];
    const float* fb1 = (const float*)d_in[21];
    const float* fW2 = (const float*)d_in[22];
    const float* fb2 = (const float*)d_in[23];
    const float* fW3 = (const float*)d_in[24];
    const float* fb3 = (const float*)d_in[25];
    float* out = (float*)d_out;

    float* buf1  = symf(g_buf1);
    float* buf2  = symf(g_buf2);
    float* pre   = symf(g_pre);
    float* scale = symf(g_scale);
    float* shift = symf(g_shift);
    float* biasl = symf(g_biaslstm);
    float* pool  = symf(g_pool);

    csr_build<<<N_GRAPHS, 256>>>(ei, ew);
    add_vec<<<4, 256>>>(bih, bhh, biasl, 1024);

    // layer 1: 1280 -> 640
    gemm_tn<<<dim3(640 / GBN, N_NODES / GBM), 256>>>(x, W1, buf1, nullptr, N_NODES, 640, 1280);
    gcn_agg<<<dim3(10, N_GRAPHS), 256>>>(buf1, b1, buf2, 640);
    bn_stats<<<640 / 32, 256>>>(buf2, ga1, be1, scale, shift, 640);
    norm_leaky<<<(N_NODES * 640 + 255) / 256, 256>>>(buf2, scale, shift, 640, N_NODES * 640);

    // layer 2: 640 -> 512
    gemm_tn<<<dim3(512 / GBN, N_NODES / GBM), 256>>>(buf2, W2, buf1, nullptr, N_NODES, 512, 640);
    gcn_agg<<<dim3(8, N_GRAPHS), 256>>>(buf1, b2, buf2, 512);
    bn_stats<<<512 / 32, 256>>>(buf2, ga2, be2, scale, shift, 512);
    norm_leaky<<<(N_NODES * 512 + 255) / 256, 256>>>(buf2, scale, shift, 512, N_NODES * 512);

    // layer 3: 512 -> 256
    gemm_tn<<<dim3(256 / GBN, N_NODES / GBM), 256>>>(buf2, W3, buf1, nullptr, N_NODES, 256, 512);
    gcn_agg<<<dim3(4, N_GRAPHS), 256>>>(buf1, b3, buf2, 256);
    bn_stats<<<256 / 32, 256>>>(buf2, ga3, be3, scale, shift, 256);
    norm_leaky<<<(N_NODES * 256 + 255) / 256, 256>>>(buf2, scale, shift, 256, N_NODES * 256);

    // LSTM input projection: pre = h3 @ Wih^T + (bih + bhh)
    gemm_tn<<<dim3(1024 / GBN, N_NODES / GBM), 256>>>(buf2, Wih, pre, biasl, N_NODES, 1024, 256);

    // sequential LSTM + fused pooling
    lstm_kernel<<<8, 512>>>(Whh, pre, pool);

    // head MLP
    fc_head<<<N_GRAPHS, 128>>>(pool, fW1, fb1, fW2, fb2, fW3, fb3, out);

    (void)in_sizes; (void)n_in; (void)out_size;
}